// round 1
// baseline (speedup 1.0000x reference)
#include <cuda_runtime.h>
#include <math.h>

#define S_LEN   2048
#define HIDDEN  2048
#define HEADS   32
#define HD      128
#define QKV_N   (3 * HEADS * HD)   // 12288
#define OD      (HEADS * HD)       // 4096

// ---------------- scratch (static device allocations, allowed) -------------
__device__ float g_qkv[(size_t)S_LEN * QKV_N];     // 100 MB
__device__ float g_q[(size_t)HEADS * S_LEN * HD];  // 33.5 MB
__device__ float g_k[(size_t)HEADS * S_LEN * HD];
__device__ float g_v[(size_t)HEADS * S_LEN * HD];
__device__ float g_o[(size_t)S_LEN * OD];          // 33.5 MB

// ---------------- SGEMM NT: C[M,N] = A[M,K] * B[N,K]^T ---------------------
// BM=BN=128, BK=16, 256 threads, 8x8 microtile. M,N,K must be multiples of tile.
__global__ __launch_bounds__(256) void sgemm_nt(const float* __restrict__ A,
                                                const float* __restrict__ B,
                                                float* __restrict__ C,
                                                int M, int N, int K)
{
    const int BM = 128, BN = 128, BK = 16;
    __shared__ float As[BK][BM];
    __shared__ float Bs[BK][BN];

    const int tid = threadIdx.x;
    const int bm0 = blockIdx.y * BM;
    const int bn0 = blockIdx.x * BN;
    const int tx = tid & 15;
    const int ty = tid >> 4;

    float acc[8][8];
#pragma unroll
    for (int i = 0; i < 8; i++)
#pragma unroll
        for (int j = 0; j < 8; j++) acc[i][j] = 0.f;

    for (int k0 = 0; k0 < K; k0 += BK) {
        // Each thread loads 2 float4 of A and 2 float4 of B (tile 128x16).
#pragma unroll
        for (int t = 0; t < 2; t++) {
            int idx = tid + t * 256;          // 0..511
            int r   = idx >> 2;               // 0..127
            int c4  = (idx & 3) * 4;          // 0,4,8,12
            float4 va = *(const float4*)&A[(size_t)(bm0 + r) * K + k0 + c4];
            As[c4 + 0][r] = va.x; As[c4 + 1][r] = va.y;
            As[c4 + 2][r] = va.z; As[c4 + 3][r] = va.w;
            float4 vb = *(const float4*)&B[(size_t)(bn0 + r) * K + k0 + c4];
            Bs[c4 + 0][r] = vb.x; Bs[c4 + 1][r] = vb.y;
            Bs[c4 + 2][r] = vb.z; Bs[c4 + 3][r] = vb.w;
        }
        __syncthreads();

#pragma unroll
        for (int kk = 0; kk < BK; kk++) {
            float a[8], b[8];
            float4 a0 = *(const float4*)&As[kk][ty * 8];
            float4 a1 = *(const float4*)&As[kk][ty * 8 + 4];
            a[0]=a0.x; a[1]=a0.y; a[2]=a0.z; a[3]=a0.w;
            a[4]=a1.x; a[5]=a1.y; a[6]=a1.z; a[7]=a1.w;
            float4 b0 = *(const float4*)&Bs[kk][tx * 8];
            float4 b1 = *(const float4*)&Bs[kk][tx * 8 + 4];
            b[0]=b0.x; b[1]=b0.y; b[2]=b0.z; b[3]=b0.w;
            b[4]=b1.x; b[5]=b1.y; b[6]=b1.z; b[7]=b1.w;
#pragma unroll
            for (int i = 0; i < 8; i++)
#pragma unroll
                for (int j = 0; j < 8; j++)
                    acc[i][j] += a[i] * b[j];
        }
        __syncthreads();
    }

#pragma unroll
    for (int i = 0; i < 8; i++) {
        int m = bm0 + ty * 8 + i;
        float4* crow = (float4*)&C[(size_t)m * N + bn0 + tx * 8];
        crow[0] = make_float4(acc[i][0], acc[i][1], acc[i][2], acc[i][3]);
        crow[1] = make_float4(acc[i][4], acc[i][5], acc[i][6], acc[i][7]);
    }
}

// ---------------- RMSNorm + RoPE + scatter to [H][S][D] --------------------
__global__ __launch_bounds__(128) void norm_rope(const float* __restrict__ qkv,
                                                 const int* __restrict__ positions,
                                                 const float* __restrict__ qw,
                                                 const float* __restrict__ kw,
                                                 float* __restrict__ gq,
                                                 float* __restrict__ gk,
                                                 float* __restrict__ gv)
{
    const int h = blockIdx.x;
    const int s = blockIdx.y;
    const int d = threadIdx.x;   // 0..127

    const float* base = qkv + (size_t)s * QKV_N + h * HD;
    float qv = base[d];
    float kv = base[HEADS * HD + d];
    float vv = base[2 * HEADS * HD + d];

    // block reduce sum of squares for q and k
    float q2 = qv * qv, k2 = kv * kv;
#pragma unroll
    for (int off = 16; off > 0; off >>= 1) {
        q2 += __shfl_xor_sync(0xffffffffu, q2, off);
        k2 += __shfl_xor_sync(0xffffffffu, k2, off);
    }
    __shared__ float sq[4], sk[4];
    int wid = d >> 5, lane = d & 31;
    if (lane == 0) { sq[wid] = q2; sk[wid] = k2; }
    __syncthreads();
    q2 = sq[0] + sq[1] + sq[2] + sq[3];
    k2 = sk[0] + sk[1] + sk[2] + sk[3];

    float qn = qv * rsqrtf(q2 * (1.f / HD) + 1e-5f) * qw[d];
    float kn = kv * rsqrtf(k2 * (1.f / HD) + 1e-5f) * kw[d];

    __shared__ float qs[HD], ks[HD];
    qs[d] = qn; ks[d] = kn;
    __syncthreads();

    const size_t out = ((size_t)h * S_LEN + s) * HD;
    gv[out + d] = vv;

    if (d < HD / 2) {
        int p = positions[s];
        // angle in double, range-reduce, then fast fp32 sincos
        double inv = exp(-log(10000.0) * (double)(2 * d) / (double)HD);
        double ang = (double)p * inv;
        const double twopi = 6.283185307179586476925286766559;
        ang -= twopi * rint(ang / twopi);
        float c, sn;
        __sincosf((float)ang, &sn, &c);

        float q1 = qs[d], q2v = qs[d + HD / 2];
        float k1 = ks[d], k2v = ks[d + HD / 2];
        gq[out + d]          = q1 * c - q2v * sn;
        gq[out + d + HD / 2] = q2v * c + q1 * sn;
        gk[out + d]          = k1 * c - k2v * sn;
        gk[out + d + HD / 2] = k2v * c + k1 * sn;
    }
}

// ---------------- flash attention, causal, fp32 ----------------------------
#define AQ   64
#define AK   64
#define TSTR 132   // padded row stride for Q/K/V tiles (floats)
#define SSTR 68    // padded row stride for score tile

#define ATTN_SMEM_FLOATS (3 * AQ * TSTR + AQ * SSTR + 3 * AQ)
#define ATTN_SMEM_BYTES  (ATTN_SMEM_FLOATS * 4)

__global__ __launch_bounds__(256) void attn_kernel(const float* __restrict__ gq,
                                                   const float* __restrict__ gk,
                                                   const float* __restrict__ gv,
                                                   float* __restrict__ go)
{
    extern __shared__ float sm[];
    float* Qs   = sm;
    float* Ks   = Qs + AQ * TSTR;
    float* Vs   = Ks + AK * TSTR;
    float* Ss   = Vs + AK * TSTR;
    float* mrow = Ss + AQ * SSTR;
    float* lrow = mrow + AQ;
    float* crow = lrow + AQ;

    const int tid = threadIdx.x;
    const int qb  = blockIdx.x;
    const int h   = blockIdx.y;
    const int tx  = tid & 15;
    const int ty  = tid >> 4;
    const float scale = 0.08838834764831845f;  // 1/sqrt(128)

    // load Q tile [AQ][HD]
    const float* qbase = gq + ((size_t)h * S_LEN + (size_t)qb * AQ) * HD;
    for (int t = tid; t < AQ * HD / 4; t += 256) {
        int r = t >> 5;            // 32 float4 per 128-float row
        int c = (t & 31) * 4;
        *(float4*)&Qs[r * TSTR + c] = *(const float4*)&qbase[r * HD + c];
    }
    if (tid < AQ) { mrow[tid] = -1e30f; lrow[tid] = 0.f; }
    __syncthreads();

    float acc[4][8];
#pragma unroll
    for (int i = 0; i < 4; i++)
#pragma unroll
        for (int j = 0; j < 8; j++) acc[i][j] = 0.f;

    for (int kb = 0; kb <= qb; kb++) {
        const float* kbase = gk + ((size_t)h * S_LEN + (size_t)kb * AK) * HD;
        const float* vbase = gv + ((size_t)h * S_LEN + (size_t)kb * AK) * HD;
        for (int t = tid; t < AK * HD / 4; t += 256) {
            int r = t >> 5;
            int c = (t & 31) * 4;
            *(float4*)&Ks[r * TSTR + c] = *(const float4*)&kbase[r * HD + c];
            *(float4*)&Vs[r * TSTR + c] = *(const float4*)&vbase[r * HD + c];
        }
        __syncthreads();

        // scores: thread owns rows r=ty*4+i, cols c=j*16+tx
        float sv[4][4];
#pragma unroll
        for (int i = 0; i < 4; i++)
#pragma unroll
            for (int j = 0; j < 4; j++) sv[i][j] = 0.f;

#pragma unroll 4
        for (int d = 0; d < HD; d += 4) {
            float4 qv[4], kv[4];
#pragma unroll
            for (int i = 0; i < 4; i++)
                qv[i] = *(const float4*)&Qs[(ty * 4 + i) * TSTR + d];
#pragma unroll
            for (int j = 0; j < 4; j++)
                kv[j] = *(const float4*)&Ks[(j * 16 + tx) * TSTR + d];
#pragma unroll
            for (int i = 0; i < 4; i++)
#pragma unroll
                for (int j = 0; j < 4; j++)
                    sv[i][j] += qv[i].x * kv[j].x + qv[i].y * kv[j].y
                              + qv[i].z * kv[j].z + qv[i].w * kv[j].w;
        }

        const bool diag = (kb == qb);
#pragma unroll
        for (int i = 0; i < 4; i++)
#pragma unroll
            for (int j = 0; j < 4; j++) {
                sv[i][j] *= scale;
                if (diag && (kb * AK + j * 16 + tx) > (qb * AQ + ty * 4 + i))
                    sv[i][j] = -1e30f;
            }

        // online softmax per row (16 lanes per row share ty)
#pragma unroll
        for (int i = 0; i < 4; i++) {
            int r = ty * 4 + i;
            float mloc = fmaxf(fmaxf(sv[i][0], sv[i][1]), fmaxf(sv[i][2], sv[i][3]));
#pragma unroll
            for (int off = 8; off > 0; off >>= 1)
                mloc = fmaxf(mloc, __shfl_xor_sync(0xffffffffu, mloc, off));
            float mold = mrow[r];
            float mnew = fmaxf(mold, mloc);
            float p0 = __expf(sv[i][0] - mnew);
            float p1 = __expf(sv[i][1] - mnew);
            float p2 = __expf(sv[i][2] - mnew);
            float p3 = __expf(sv[i][3] - mnew);
            float sum = p0 + p1 + p2 + p3;
#pragma unroll
            for (int off = 8; off > 0; off >>= 1)
                sum += __shfl_xor_sync(0xffffffffu, sum, off);
            float corf = __expf(mold - mnew);
            if (tx == 0) {
                mrow[r] = mnew;
                lrow[r] = lrow[r] * corf + sum;
                crow[r] = corf;
            }
            Ss[r * SSTR + 0 * 16 + tx] = p0;
            Ss[r * SSTR + 1 * 16 + tx] = p1;
            Ss[r * SSTR + 2 * 16 + tx] = p2;
            Ss[r * SSTR + 3 * 16 + tx] = p3;
        }
        __syncthreads();

        // rescale + PV : O[r][c] = O*cor + P[r][:] * V[:][c]
#pragma unroll
        for (int i = 0; i < 4; i++) {
            float cf = crow[ty * 4 + i];
#pragma unroll
            for (int j = 0; j < 8; j++) acc[i][j] *= cf;
        }
#pragma unroll 8
        for (int kk = 0; kk < AK; kk++) {
            float p[4];
#pragma unroll
            for (int i = 0; i < 4; i++) p[i] = Ss[(ty * 4 + i) * SSTR + kk];
            float4 v0 = *(const float4*)&Vs[kk * TSTR + tx * 8];
            float4 v1 = *(const float4*)&Vs[kk * TSTR + tx * 8 + 4];
#pragma unroll
            for (int i = 0; i < 4; i++) {
                acc[i][0] += p[i] * v0.x; acc[i][1] += p[i] * v0.y;
                acc[i][2] += p[i] * v0.z; acc[i][3] += p[i] * v0.w;
                acc[i][4] += p[i] * v1.x; acc[i][5] += p[i] * v1.y;
                acc[i][6] += p[i] * v1.z; acc[i][7] += p[i] * v1.w;
            }
        }
        __syncthreads();
    }

    // epilogue: divide by l, write O[s][h*128 + c]
#pragma unroll
    for (int i = 0; i < 4; i++) {
        int r = ty * 4 + i;
        float inv = 1.f / lrow[r];
        int srow = qb * AQ + r;
        float* orow = go + (size_t)srow * OD + h * HD + tx * 8;
        float4 o0 = make_float4(acc[i][0]*inv, acc[i][1]*inv, acc[i][2]*inv, acc[i][3]*inv);
        float4 o1 = make_float4(acc[i][4]*inv, acc[i][5]*inv, acc[i][6]*inv, acc[i][7]*inv);
        *(float4*)&orow[0] = o0;
        *(float4*)&orow[4] = o1;
    }
}

// ---------------- launch ---------------------------------------------------
extern "C" void kernel_launch(void* const* d_in, const int* in_sizes, int n_in,
                              void* d_out, int out_size)
{
    const float* hidden    = (const float*)d_in[0];
    const int*   positions = (const int*)  d_in[1];
    const float* qkv_w     = (const float*)d_in[2];
    const float* q_norm_w  = (const float*)d_in[3];
    const float* k_norm_w  = (const float*)d_in[4];
    const float* o_proj_w  = (const float*)d_in[5];
    float* out = (float*)d_out;

    float *p_qkv, *p_q, *p_k, *p_v, *p_o;
    cudaGetSymbolAddress((void**)&p_qkv, g_qkv);
    cudaGetSymbolAddress((void**)&p_q,   g_q);
    cudaGetSymbolAddress((void**)&p_k,   g_k);
    cudaGetSymbolAddress((void**)&p_v,   g_v);
    cudaGetSymbolAddress((void**)&p_o,   g_o);

    // 1) QKV GEMM: [2048,12288] = hidden[2048,2048] * qkv_w[12288,2048]^T
    sgemm_nt<<<dim3(QKV_N / 128, S_LEN / 128), 256>>>(hidden, qkv_w, p_qkv,
                                                      S_LEN, QKV_N, HIDDEN);

    // 2) RMSNorm + RoPE + scatter to [H][S][D]
    norm_rope<<<dim3(HEADS, S_LEN), 128>>>(p_qkv, positions, q_norm_w, k_norm_w,
                                           p_q, p_k, p_v);

    // 3) causal flash attention
    cudaFuncSetAttribute(attn_kernel, cudaFuncAttributeMaxDynamicSharedMemorySize,
                         ATTN_SMEM_BYTES);
    attn_kernel<<<dim3(S_LEN / AQ, HEADS), 256, ATTN_SMEM_BYTES>>>(p_q, p_k, p_v, p_o);

    // 4) O projection: out[2048,2048] = o[2048,4096] * o_proj_w[2048,4096]^T
    sgemm_nt<<<dim3(HIDDEN / 128, S_LEN / 128), 256>>>(p_o, o_proj_w, out,
                                                       S_LEN, HIDDEN, OD);
}

// round 4
// speedup vs baseline: 2.0310x; 2.0310x over previous
#include <cuda_runtime.h>
#include <cuda_fp16.h>
#include <math.h>
#include <cstdint>

#define S_LEN   2048
#define HIDDEN  2048
#define HEADS   32
#define HD      128
#define QKV_N   (3 * HEADS * HD)   // 12288
#define OD      (HEADS * HD)       // 4096

// ---------------- scratch ---------------------------------------------------
__device__ float g_qkv[(size_t)S_LEN * QKV_N];
__device__ float g_q[(size_t)HEADS * S_LEN * HD];
__device__ float g_k[(size_t)HEADS * S_LEN * HD];
__device__ float g_v[(size_t)HEADS * S_LEN * HD];
__device__ float g_o[(size_t)S_LEN * OD];

// ---------------- fp16 HMMA GEMM NT: C[M,N] = A[M,K] * B[N,K]^T --------------
// 128x128x32 block tile, 256 threads (8 warps, 2x4), warp tile 64x32.
// mma.sync.m16n8k16 row.col f32.f16.f16.f32 — fragments loaded with plain LDS
// using the canonical lane mapping; KPAD=40 makes those LDS conflict-free.
#define BKG  32
#define KPAD 40

__device__ __forceinline__ uint32_t pack_h2(float a, float b) {
    __half2 h = __floats2half2_rn(a, b);
    return *reinterpret_cast<uint32_t*>(&h);
}

__device__ __forceinline__ void mma_f16(float& d0, float& d1, float& d2, float& d3,
                                        uint32_t a0, uint32_t a1, uint32_t a2, uint32_t a3,
                                        uint32_t b0, uint32_t b1) {
    asm volatile(
        "mma.sync.aligned.m16n8k16.row.col.f32.f16.f16.f32 "
        "{%0,%1,%2,%3}, {%4,%5,%6,%7}, {%8,%9}, {%0,%1,%2,%3};"
        : "+f"(d0), "+f"(d1), "+f"(d2), "+f"(d3)
        : "r"(a0), "r"(a1), "r"(a2), "r"(a3), "r"(b0), "r"(b1));
}

__global__ __launch_bounds__(256) void gemm_hmma(const float* __restrict__ A,
                                                 const float* __restrict__ B,
                                                 float* __restrict__ C,
                                                 int M, int N, int K)
{
    __shared__ uint16_t As[128 * KPAD];
    __shared__ uint16_t Bs[128 * KPAD];

    const int tid  = threadIdx.x;
    const int wid  = tid >> 5;
    const int lane = tid & 31;
    const int g    = lane >> 2;       // group 0..7
    const int t    = lane & 3;        // thread-in-group 0..3
    const int wm   = (wid >> 2) * 64; // 0 or 64
    const int wn   = (wid & 3) * 32;  // 0,32,64,96
    const int bm0  = blockIdx.y * 128;
    const int bn0  = blockIdx.x * 128;

    float acc[4][4][4];
#pragma unroll
    for (int i = 0; i < 4; i++)
#pragma unroll
        for (int j = 0; j < 4; j++)
#pragma unroll
            for (int r = 0; r < 4; r++) acc[i][j][r] = 0.f;

    for (int k0 = 0; k0 < K; k0 += BKG) {
        // fill tiles: 128 rows x 32 cols fp32 -> fp16 (each thread 4 float4 per tensor)
#pragma unroll
        for (int i = 0; i < 4; i++) {
            int idx = tid + i * 256;      // 0..1023
            int r   = idx >> 3;           // 0..127
            int c4  = (idx & 7) * 4;      // 0,4,...,28
            float4 va = *(const float4*)&A[(size_t)(bm0 + r) * K + k0 + c4];
            uint2 pa = make_uint2(pack_h2(va.x, va.y), pack_h2(va.z, va.w));
            *(uint2*)&As[r * KPAD + c4] = pa;
            float4 vb = *(const float4*)&B[(size_t)(bn0 + r) * K + k0 + c4];
            uint2 pb = make_uint2(pack_h2(vb.x, vb.y), pack_h2(vb.z, vb.w));
            *(uint2*)&Bs[r * KPAD + c4] = pb;
        }
        __syncthreads();

#pragma unroll
        for (int kk = 0; kk < BKG; kk += 16) {
            uint32_t af[4][4], bf[4][2];
#pragma unroll
            for (int mt = 0; mt < 4; mt++) {
                int rb = wm + mt * 16;
                af[mt][0] = *(const uint32_t*)&As[(rb + g    ) * KPAD + kk + 2 * t    ];
                af[mt][1] = *(const uint32_t*)&As[(rb + g + 8) * KPAD + kk + 2 * t    ];
                af[mt][2] = *(const uint32_t*)&As[(rb + g    ) * KPAD + kk + 2 * t + 8];
                af[mt][3] = *(const uint32_t*)&As[(rb + g + 8) * KPAD + kk + 2 * t + 8];
            }
#pragma unroll
            for (int nt = 0; nt < 4; nt++) {
                int nb = wn + nt * 8;
                bf[nt][0] = *(const uint32_t*)&Bs[(nb + g) * KPAD + kk + 2 * t    ];
                bf[nt][1] = *(const uint32_t*)&Bs[(nb + g) * KPAD + kk + 2 * t + 8];
            }
#pragma unroll
            for (int mt = 0; mt < 4; mt++)
#pragma unroll
                for (int nt = 0; nt < 4; nt++)
                    mma_f16(acc[mt][nt][0], acc[mt][nt][1], acc[mt][nt][2], acc[mt][nt][3],
                            af[mt][0], af[mt][1], af[mt][2], af[mt][3],
                            bf[nt][0], bf[nt][1]);
        }
        __syncthreads();
    }

    // epilogue: d0:(g,2t) d1:(g,2t+1) d2:(g+8,2t) d3:(g+8,2t+1)
#pragma unroll
    for (int mt = 0; mt < 4; mt++) {
        int row0 = bm0 + wm + mt * 16 + g;
#pragma unroll
        for (int nt = 0; nt < 4; nt++) {
            int col = bn0 + wn + nt * 8 + 2 * t;
            *(float2*)&C[(size_t)row0 * N + col] =
                make_float2(acc[mt][nt][0], acc[mt][nt][1]);
            *(float2*)&C[(size_t)(row0 + 8) * N + col] =
                make_float2(acc[mt][nt][2], acc[mt][nt][3]);
        }
    }
}

// ---------------- RMSNorm + RoPE + scatter to [H][S][D] ----------------------
__global__ __launch_bounds__(128) void norm_rope(const float* __restrict__ qkv,
                                                 const int* __restrict__ positions,
                                                 const float* __restrict__ qw,
                                                 const float* __restrict__ kw,
                                                 float* __restrict__ gq,
                                                 float* __restrict__ gk,
                                                 float* __restrict__ gv)
{
    const int h = blockIdx.x;
    const int s = blockIdx.y;
    const int d = threadIdx.x;

    const float* base = qkv + (size_t)s * QKV_N + h * HD;
    float qv = base[d];
    float kv = base[HEADS * HD + d];
    float vv = base[2 * HEADS * HD + d];

    float q2 = qv * qv, k2 = kv * kv;
#pragma unroll
    for (int off = 16; off > 0; off >>= 1) {
        q2 += __shfl_xor_sync(0xffffffffu, q2, off);
        k2 += __shfl_xor_sync(0xffffffffu, k2, off);
    }
    __shared__ float sq[4], sk[4];
    int wid = d >> 5, lane = d & 31;
    if (lane == 0) { sq[wid] = q2; sk[wid] = k2; }
    __syncthreads();
    q2 = sq[0] + sq[1] + sq[2] + sq[3];
    k2 = sk[0] + sk[1] + sk[2] + sk[3];

    float qn = qv * rsqrtf(q2 * (1.f / HD) + 1e-5f) * qw[d];
    float kn = kv * rsqrtf(k2 * (1.f / HD) + 1e-5f) * kw[d];

    __shared__ float qs[HD], ks[HD];
    qs[d] = qn; ks[d] = kn;
    __syncthreads();

    const size_t out = ((size_t)h * S_LEN + s) * HD;
    gv[out + d] = vv;

    if (d < HD / 2) {
        int p = positions[s];
        double inv = exp(-log(10000.0) * (double)(2 * d) / (double)HD);
        double ang = (double)p * inv;
        const double twopi = 6.283185307179586476925286766559;
        ang -= twopi * rint(ang / twopi);
        float c, sn;
        __sincosf((float)ang, &sn, &c);

        float q1 = qs[d], q2v = qs[d + HD / 2];
        float k1 = ks[d], k2v = ks[d + HD / 2];
        gq[out + d]          = q1 * c - q2v * sn;
        gq[out + d + HD / 2] = q2v * c + q1 * sn;
        gk[out + d]          = k1 * c - k2v * sn;
        gk[out + d + HD / 2] = k2v * c + k1 * sn;
    }
}

// ---------------- flash attention, causal, fp32 ------------------------------
#define AQ   64
#define AK   64
#define TSTR 132
#define SSTR 68

#define ATTN_SMEM_FLOATS (3 * AQ * TSTR + AQ * SSTR + 3 * AQ)
#define ATTN_SMEM_BYTES  (ATTN_SMEM_FLOATS * 4)

__global__ __launch_bounds__(256) void attn_kernel(const float* __restrict__ gq,
                                                   const float* __restrict__ gk,
                                                   const float* __restrict__ gv,
                                                   float* __restrict__ go)
{
    extern __shared__ float smf[];
    float* Qs   = smf;
    float* Ks   = Qs + AQ * TSTR;
    float* Vs   = Ks + AK * TSTR;
    float* Ss   = Vs + AK * TSTR;
    float* mrow = Ss + AQ * SSTR;
    float* lrow = mrow + AQ;
    float* crow = lrow + AQ;

    const int tid = threadIdx.x;
    const int qb  = blockIdx.x;
    const int h   = blockIdx.y;
    const int tx  = tid & 15;
    const int ty  = tid >> 4;
    const float scale = 0.08838834764831845f;

    const float* qbase = gq + ((size_t)h * S_LEN + (size_t)qb * AQ) * HD;
    for (int t = tid; t < AQ * HD / 4; t += 256) {
        int r = t >> 5;
        int c = (t & 31) * 4;
        *(float4*)&Qs[r * TSTR + c] = *(const float4*)&qbase[r * HD + c];
    }
    if (tid < AQ) { mrow[tid] = -1e30f; lrow[tid] = 0.f; }
    __syncthreads();

    float acc[4][8];
#pragma unroll
    for (int i = 0; i < 4; i++)
#pragma unroll
        for (int j = 0; j < 8; j++) acc[i][j] = 0.f;

    for (int kb = 0; kb <= qb; kb++) {
        const float* kbase = gk + ((size_t)h * S_LEN + (size_t)kb * AK) * HD;
        const float* vbase = gv + ((size_t)h * S_LEN + (size_t)kb * AK) * HD;
        for (int t = tid; t < AK * HD / 4; t += 256) {
            int r = t >> 5;
            int c = (t & 31) * 4;
            *(float4*)&Ks[r * TSTR + c] = *(const float4*)&kbase[r * HD + c];
            *(float4*)&Vs[r * TSTR + c] = *(const float4*)&vbase[r * HD + c];
        }
        __syncthreads();

        float sv[4][4];
#pragma unroll
        for (int i = 0; i < 4; i++)
#pragma unroll
            for (int j = 0; j < 4; j++) sv[i][j] = 0.f;

#pragma unroll 4
        for (int d = 0; d < HD; d += 4) {
            float4 qv[4], kv[4];
#pragma unroll
            for (int i = 0; i < 4; i++)
                qv[i] = *(const float4*)&Qs[(ty * 4 + i) * TSTR + d];
#pragma unroll
            for (int j = 0; j < 4; j++)
                kv[j] = *(const float4*)&Ks[(j * 16 + tx) * TSTR + d];
#pragma unroll
            for (int i = 0; i < 4; i++)
#pragma unroll
                for (int j = 0; j < 4; j++)
                    sv[i][j] += qv[i].x * kv[j].x + qv[i].y * kv[j].y
                              + qv[i].z * kv[j].z + qv[i].w * kv[j].w;
        }

        const bool diag = (kb == qb);
#pragma unroll
        for (int i = 0; i < 4; i++)
#pragma unroll
            for (int j = 0; j < 4; j++) {
                sv[i][j] *= scale;
                if (diag && (kb * AK + j * 16 + tx) > (qb * AQ + ty * 4 + i))
                    sv[i][j] = -1e30f;
            }

#pragma unroll
        for (int i = 0; i < 4; i++) {
            int r = ty * 4 + i;
            float mloc = fmaxf(fmaxf(sv[i][0], sv[i][1]), fmaxf(sv[i][2], sv[i][3]));
#pragma unroll
            for (int off = 8; off > 0; off >>= 1)
                mloc = fmaxf(mloc, __shfl_xor_sync(0xffffffffu, mloc, off));
            float mold = mrow[r];
            float mnew = fmaxf(mold, mloc);
            float p0 = __expf(sv[i][0] - mnew);
            float p1 = __expf(sv[i][1] - mnew);
            float p2 = __expf(sv[i][2] - mnew);
            float p3 = __expf(sv[i][3] - mnew);
            float sum = p0 + p1 + p2 + p3;
#pragma unroll
            for (int off = 8; off > 0; off >>= 1)
                sum += __shfl_xor_sync(0xffffffffu, sum, off);
            float corf = __expf(mold - mnew);
            if (tx == 0) {
                mrow[r] = mnew;
                lrow[r] = lrow[r] * corf + sum;
                crow[r] = corf;
            }
            Ss[r * SSTR + 0 * 16 + tx] = p0;
            Ss[r * SSTR + 1 * 16 + tx] = p1;
            Ss[r * SSTR + 2 * 16 + tx] = p2;
            Ss[r * SSTR + 3 * 16 + tx] = p3;
        }
        __syncthreads();

#pragma unroll
        for (int i = 0; i < 4; i++) {
            float cf = crow[ty * 4 + i];
#pragma unroll
            for (int j = 0; j < 8; j++) acc[i][j] *= cf;
        }
#pragma unroll 8
        for (int kk = 0; kk < AK; kk++) {
            float p[4];
#pragma unroll
            for (int i = 0; i < 4; i++) p[i] = Ss[(ty * 4 + i) * SSTR + kk];
            float4 v0 = *(const float4*)&Vs[kk * TSTR + tx * 8];
            float4 v1 = *(const float4*)&Vs[kk * TSTR + tx * 8 + 4];
#pragma unroll
            for (int i = 0; i < 4; i++) {
                acc[i][0] += p[i] * v0.x; acc[i][1] += p[i] * v0.y;
                acc[i][2] += p[i] * v0.z; acc[i][3] += p[i] * v0.w;
                acc[i][4] += p[i] * v1.x; acc[i][5] += p[i] * v1.y;
                acc[i][6] += p[i] * v1.z; acc[i][7] += p[i] * v1.w;
            }
        }
        __syncthreads();
    }

#pragma unroll
    for (int i = 0; i < 4; i++) {
        int r = ty * 4 + i;
        float inv = 1.f / lrow[r];
        int srow = qb * AQ + r;
        float* orow = go + (size_t)srow * OD + h * HD + tx * 8;
        float4 o0 = make_float4(acc[i][0]*inv, acc[i][1]*inv, acc[i][2]*inv, acc[i][3]*inv);
        float4 o1 = make_float4(acc[i][4]*inv, acc[i][5]*inv, acc[i][6]*inv, acc[i][7]*inv);
        *(float4*)&orow[0] = o0;
        *(float4*)&orow[4] = o1;
    }
}

// ---------------- launch -----------------------------------------------------
extern "C" void kernel_launch(void* const* d_in, const int* in_sizes, int n_in,
                              void* d_out, int out_size)
{
    const float* hidden    = (const float*)d_in[0];
    const int*   positions = (const int*)  d_in[1];
    const float* qkv_w     = (const float*)d_in[2];
    const float* q_norm_w  = (const float*)d_in[3];
    const float* k_norm_w  = (const float*)d_in[4];
    const float* o_proj_w  = (const float*)d_in[5];
    float* out = (float*)d_out;

    float *p_qkv, *p_q, *p_k, *p_v, *p_o;
    cudaGetSymbolAddress((void**)&p_qkv, g_qkv);
    cudaGetSymbolAddress((void**)&p_q,   g_q);
    cudaGetSymbolAddress((void**)&p_k,   g_k);
    cudaGetSymbolAddress((void**)&p_v,   g_v);
    cudaGetSymbolAddress((void**)&p_o,   g_o);

    cudaFuncSetAttribute(attn_kernel, cudaFuncAttributeMaxDynamicSharedMemorySize,
                         ATTN_SMEM_BYTES);

    // 1) QKV GEMM: [2048,12288] = hidden[2048,2048] * qkv_w[12288,2048]^T
    gemm_hmma<<<dim3(QKV_N / 128, S_LEN / 128), 256>>>(hidden, qkv_w, p_qkv,
                                                       S_LEN, QKV_N, HIDDEN);

    // 2) RMSNorm + RoPE + scatter
    norm_rope<<<dim3(HEADS, S_LEN), 128>>>(p_qkv, positions, q_norm_w, k_norm_w,
                                           p_q, p_k, p_v);

    // 3) causal flash attention (fp32)
    attn_kernel<<<dim3(S_LEN / AQ, HEADS), 256, ATTN_SMEM_BYTES>>>(p_q, p_k, p_v, p_o);

    // 4) O projection: out[2048,2048] = o[2048,4096] * o_proj_w[2048,4096]^T
    gemm_hmma<<<dim3(HIDDEN / 128, S_LEN / 128), 256>>>(p_o, o_proj_w, out,
                                                        S_LEN, HIDDEN, OD);
}

// round 5
// speedup vs baseline: 3.1592x; 1.5555x over previous
#include <cuda_runtime.h>
#include <cuda_fp16.h>
#include <math.h>
#include <cstdint>

#define S_LEN   2048
#define HIDDEN  2048
#define HEADS   32
#define HD      128
#define QKV_N   (3 * HEADS * HD)   // 12288
#define OD      (HEADS * HD)       // 4096

// ---------------- scratch ---------------------------------------------------
__device__ float  g_qkv[(size_t)S_LEN * QKV_N];     // 100 MB
__device__ float  g_o[(size_t)S_LEN * OD];          // 33.5 MB
#define HSZ ((size_t)HEADS * S_LEN * HD)
__device__ __half g_qh[HSZ], g_ql[HSZ];
__device__ __half g_kh[HSZ], g_kl[HSZ];
__device__ __half g_vh[HSZ], g_vl[HSZ];

// ---------------- mma / ldmatrix helpers ------------------------------------
__device__ __forceinline__ uint32_t smem_u32(const void* p) {
    uint32_t a;
    asm("{ .reg .u64 t; cvta.to.shared.u64 t, %1; cvt.u32.u64 %0, t; }" : "=r"(a) : "l"(p));
    return a;
}
__device__ __forceinline__ uint32_t pack_h2(float a, float b) {
    __half2 h = __floats2half2_rn(a, b);
    return *reinterpret_cast<uint32_t*>(&h);
}
__device__ __forceinline__ uint32_t pack_hh(__half a, __half b) {
    __half2 h = __halves2half2(a, b);
    return *reinterpret_cast<uint32_t*>(&h);
}
__device__ __forceinline__ void mma_f16(float* d, const uint32_t* a,
                                        uint32_t b0, uint32_t b1) {
    asm volatile(
        "mma.sync.aligned.m16n8k16.row.col.f32.f16.f16.f32 "
        "{%0,%1,%2,%3}, {%4,%5,%6,%7}, {%8,%9}, {%0,%1,%2,%3};"
        : "+f"(d[0]), "+f"(d[1]), "+f"(d[2]), "+f"(d[3])
        : "r"(a[0]), "r"(a[1]), "r"(a[2]), "r"(a[3]), "r"(b0), "r"(b1));
}
__device__ __forceinline__ void ldsm_x4(uint32_t* r, uint32_t addr) {
    asm volatile("ldmatrix.sync.aligned.m8n8.x4.shared.b16 {%0,%1,%2,%3}, [%4];"
        : "=r"(r[0]), "=r"(r[1]), "=r"(r[2]), "=r"(r[3]) : "r"(addr));
}
__device__ __forceinline__ void ldsm_x4_t(uint32_t* r, uint32_t addr) {
    asm volatile("ldmatrix.sync.aligned.m8n8.x4.trans.shared.b16 {%0,%1,%2,%3}, [%4];"
        : "=r"(r[0]), "=r"(r[1]), "=r"(r[2]), "=r"(r[3]) : "r"(addr));
}

// ---------------- fp16 HMMA GEMM NT: C[M,N] = A[M,K] * B[N,K]^T --------------
#define BKG  32
#define KPAD 40

__global__ __launch_bounds__(256) void gemm_hmma(const float* __restrict__ A,
                                                 const float* __restrict__ B,
                                                 float* __restrict__ C,
                                                 int M, int N, int K)
{
    __shared__ uint16_t As[128 * KPAD];
    __shared__ uint16_t Bs[128 * KPAD];

    const int tid  = threadIdx.x;
    const int wid  = tid >> 5;
    const int lane = tid & 31;
    const int g    = lane >> 2;
    const int t    = lane & 3;
    const int wm   = (wid >> 2) * 64;
    const int wn   = (wid & 3) * 32;
    const int bm0  = blockIdx.y * 128;
    const int bn0  = blockIdx.x * 128;

    float acc[4][4][4];
#pragma unroll
    for (int i = 0; i < 4; i++)
#pragma unroll
        for (int j = 0; j < 4; j++)
#pragma unroll
            for (int r = 0; r < 4; r++) acc[i][j][r] = 0.f;

    for (int k0 = 0; k0 < K; k0 += BKG) {
#pragma unroll
        for (int i = 0; i < 4; i++) {
            int idx = tid + i * 256;
            int r   = idx >> 3;
            int c4  = (idx & 7) * 4;
            float4 va = *(const float4*)&A[(size_t)(bm0 + r) * K + k0 + c4];
            *(uint2*)&As[r * KPAD + c4] = make_uint2(pack_h2(va.x, va.y), pack_h2(va.z, va.w));
            float4 vb = *(const float4*)&B[(size_t)(bn0 + r) * K + k0 + c4];
            *(uint2*)&Bs[r * KPAD + c4] = make_uint2(pack_h2(vb.x, vb.y), pack_h2(vb.z, vb.w));
        }
        __syncthreads();

#pragma unroll
        for (int kk = 0; kk < BKG; kk += 16) {
            uint32_t af[4][4], bf[4][2];
#pragma unroll
            for (int mt = 0; mt < 4; mt++) {
                int rb = wm + mt * 16;
                af[mt][0] = *(const uint32_t*)&As[(rb + g    ) * KPAD + kk + 2 * t    ];
                af[mt][1] = *(const uint32_t*)&As[(rb + g + 8) * KPAD + kk + 2 * t    ];
                af[mt][2] = *(const uint32_t*)&As[(rb + g    ) * KPAD + kk + 2 * t + 8];
                af[mt][3] = *(const uint32_t*)&As[(rb + g + 8) * KPAD + kk + 2 * t + 8];
            }
#pragma unroll
            for (int nt = 0; nt < 4; nt++) {
                int nb = wn + nt * 8;
                bf[nt][0] = *(const uint32_t*)&Bs[(nb + g) * KPAD + kk + 2 * t    ];
                bf[nt][1] = *(const uint32_t*)&Bs[(nb + g) * KPAD + kk + 2 * t + 8];
            }
#pragma unroll
            for (int mt = 0; mt < 4; mt++)
#pragma unroll
                for (int nt = 0; nt < 4; nt++)
                    mma_f16(acc[mt][nt], af[mt], bf[nt][0], bf[nt][1]);
        }
        __syncthreads();
    }

#pragma unroll
    for (int mt = 0; mt < 4; mt++) {
        int row0 = bm0 + wm + mt * 16 + g;
#pragma unroll
        for (int nt = 0; nt < 4; nt++) {
            int col = bn0 + wn + nt * 8 + 2 * t;
            *(float2*)&C[(size_t)row0 * N + col] = make_float2(acc[mt][nt][0], acc[mt][nt][1]);
            *(float2*)&C[(size_t)(row0 + 8) * N + col] = make_float2(acc[mt][nt][2], acc[mt][nt][3]);
        }
    }
}

// ---------------- RMSNorm + RoPE + hi/lo fp16 scatter ------------------------
__device__ __forceinline__ void split_store(__half* ph, __half* pl, size_t i, float x) {
    __half h = __float2half_rn(x);
    ph[i] = h;
    pl[i] = __float2half_rn(x - __half2float(h));
}

__global__ __launch_bounds__(128) void norm_rope(const float* __restrict__ qkv,
                                                 const int* __restrict__ positions,
                                                 const float* __restrict__ qw,
                                                 const float* __restrict__ kw)
{
    const int h = blockIdx.x;
    const int s = blockIdx.y;
    const int d = threadIdx.x;

    const float* base = qkv + (size_t)s * QKV_N + h * HD;
    float qv = base[d];
    float kv = base[HEADS * HD + d];
    float vv = base[2 * HEADS * HD + d];

    float q2 = qv * qv, k2 = kv * kv;
#pragma unroll
    for (int off = 16; off > 0; off >>= 1) {
        q2 += __shfl_xor_sync(0xffffffffu, q2, off);
        k2 += __shfl_xor_sync(0xffffffffu, k2, off);
    }
    __shared__ float sq[4], sk[4];
    int wid = d >> 5, lane = d & 31;
    if (lane == 0) { sq[wid] = q2; sk[wid] = k2; }
    __syncthreads();
    q2 = sq[0] + sq[1] + sq[2] + sq[3];
    k2 = sk[0] + sk[1] + sk[2] + sk[3];

    float qn = qv * rsqrtf(q2 * (1.f / HD) + 1e-5f) * qw[d];
    float kn = kv * rsqrtf(k2 * (1.f / HD) + 1e-5f) * kw[d];

    __shared__ float qs[HD], ks[HD];
    qs[d] = qn; ks[d] = kn;
    __syncthreads();

    const size_t out = ((size_t)h * S_LEN + s) * HD;
    split_store(g_vh, g_vl, out + d, vv);

    if (d < HD / 2) {
        int p = positions[s];
        double inv = exp(-log(10000.0) * (double)(2 * d) / (double)HD);
        double ang = (double)p * inv;
        const double twopi = 6.283185307179586476925286766559;
        ang -= twopi * rint(ang / twopi);
        float c, sn;
        __sincosf((float)ang, &sn, &c);

        float q1 = qs[d], q2v = qs[d + HD / 2];
        float k1 = ks[d], k2v = ks[d + HD / 2];
        split_store(g_qh, g_ql, out + d,          q1 * c - q2v * sn);
        split_store(g_qh, g_ql, out + d + HD / 2, q2v * c + q1 * sn);
        split_store(g_kh, g_kl, out + d,          k1 * c - k2v * sn);
        split_store(g_kh, g_kl, out + d + HD / 2, k2v * c + k1 * sn);
    }
}

// ---------------- tensor-core flash attention (hi/lo fp16, fp32 softmax) -----
#define BQ  128
#define BK  64
#define HDP 136   // halves per tile row (272B stride: 16B-aligned, ldmatrix-friendly)

#define ATTN_SMEM ((2 * BQ + 4 * BK) * HDP * 2)   // 139264 bytes

__global__ __launch_bounds__(256) void attn_mma(const __half* __restrict__ qh,
                                                const __half* __restrict__ ql,
                                                const __half* __restrict__ kh,
                                                const __half* __restrict__ kl,
                                                const __half* __restrict__ vh,
                                                const __half* __restrict__ vl,
                                                float* __restrict__ go)
{
    extern __shared__ __half sh[];
    __half* Qh = sh;
    __half* Ql = Qh + BQ * HDP;
    __half* Kh = Ql + BQ * HDP;
    __half* Kl = Kh + BK * HDP;
    __half* Vh = Kl + BK * HDP;
    __half* Vl = Vh + BK * HDP;

    const int tid = threadIdx.x;
    const int wq  = tid >> 5;
    const int l   = tid & 31;
    const int g   = l >> 2;
    const int t   = l & 3;
    const int qb  = gridDim.x - 1 - blockIdx.x;   // heavy blocks first
    const int h   = blockIdx.y;
    const int rb  = wq * 16;
    const float scale = 0.08838834764831845f;

    // load Q hi/lo tile
    const size_t qoff = ((size_t)h * S_LEN + (size_t)qb * BQ) * HD;
    for (int idx = tid; idx < BQ * HD / 8; idx += 256) {
        int r = idx >> 4, c = (idx & 15) * 8;
        *(uint4*)&Qh[r * HDP + c] = *(const uint4*)&qh[qoff + r * HD + c];
        *(uint4*)&Ql[r * HDP + c] = *(const uint4*)&ql[qoff + r * HD + c];
    }

    float oacc[16][4];
#pragma unroll
    for (int i = 0; i < 16; i++)
#pragma unroll
        for (int j = 0; j < 4; j++) oacc[i][j] = 0.f;
    float m_a = -1e30f, m_b = -1e30f, l_a = 0.f, l_b = 0.f;

    // per-lane ldmatrix byte addresses
    const uint32_t smb = smem_u32(sh);
    const int frag  = (l & 7) + 8 * ((l >> 3) & 1);          // row-in-16 for A/trans-B
    const int qvoff = frag * HDP + 8 * (l >> 4);             // Q (A-frag) and V (trans B)
    const int koff  = ((l & 7) + 8 * (l >> 4)) * HDP + 8 * ((l >> 3) & 1);  // K (B-frag)
    const uint32_t aQh = smb + (uint32_t)(rb * HDP + qvoff) * 2;
    const uint32_t aQl = aQh + BQ * HDP * 2;
    const uint32_t aKh = smb + (uint32_t)(2 * BQ * HDP + koff) * 2;
    const uint32_t aKl = aKh + BK * HDP * 2;
    const uint32_t aVh = smb + (uint32_t)((2 * BQ + 2 * BK) * HDP + qvoff) * 2;
    const uint32_t aVl = aVh + BK * HDP * 2;

    const int row_a = qb * BQ + rb + g;
    const int row_b = row_a + 8;
    const int nkt = 2 * qb + 2;

    for (int kb = 0; kb < nkt; kb++) {
        __syncthreads();  // previous tile's consumers done
        const size_t koff_g = ((size_t)h * S_LEN + (size_t)kb * BK) * HD;
        for (int idx = tid; idx < BK * HD / 8; idx += 256) {
            int r = idx >> 4, c = (idx & 15) * 8;
            size_t sgl = koff_g + r * HD + c;
            int dst = r * HDP + c;
            *(uint4*)&Kh[dst] = *(const uint4*)&kh[sgl];
            *(uint4*)&Kl[dst] = *(const uint4*)&kl[sgl];
            *(uint4*)&Vh[dst] = *(const uint4*)&vh[sgl];
            *(uint4*)&Vl[dst] = *(const uint4*)&vl[sgl];
        }
        __syncthreads();

        // ---- S = Q K^T (hi*hi + hi*lo + lo*hi) ----
        float sacc[8][4];
#pragma unroll
        for (int i = 0; i < 8; i++)
#pragma unroll
            for (int j = 0; j < 4; j++) sacc[i][j] = 0.f;

#pragma unroll
        for (int ks = 0; ks < 8; ks++) {
            uint32_t qhf[4], qlf[4];
            ldsm_x4(qhf, aQh + ks * 32);
            ldsm_x4(qlf, aQl + ks * 32);
#pragma unroll
            for (int np = 0; np < 4; np++) {
                uint32_t khf[4], klf[4];
                ldsm_x4(khf, aKh + np * (16 * HDP * 2) + ks * 32);
                ldsm_x4(klf, aKl + np * (16 * HDP * 2) + ks * 32);
                mma_f16(sacc[2 * np],     qhf, khf[0], khf[1]);
                mma_f16(sacc[2 * np],     qhf, klf[0], klf[1]);
                mma_f16(sacc[2 * np],     qlf, khf[0], khf[1]);
                mma_f16(sacc[2 * np + 1], qhf, khf[2], khf[3]);
                mma_f16(sacc[2 * np + 1], qhf, klf[2], klf[3]);
                mma_f16(sacc[2 * np + 1], qlf, khf[2], khf[3]);
            }
        }

        // ---- scale + causal mask + online softmax ----
        float mx_a = -1e30f, mx_b = -1e30f;
#pragma unroll
        for (int nt = 0; nt < 8; nt++) {
            int c0 = kb * BK + nt * 8 + 2 * t, c1 = c0 + 1;
            float s0 = sacc[nt][0] * scale; if (c0 > row_a) s0 = -1e30f;
            float s1 = sacc[nt][1] * scale; if (c1 > row_a) s1 = -1e30f;
            float s2 = sacc[nt][2] * scale; if (c0 > row_b) s2 = -1e30f;
            float s3 = sacc[nt][3] * scale; if (c1 > row_b) s3 = -1e30f;
            sacc[nt][0] = s0; sacc[nt][1] = s1; sacc[nt][2] = s2; sacc[nt][3] = s3;
            mx_a = fmaxf(mx_a, fmaxf(s0, s1));
            mx_b = fmaxf(mx_b, fmaxf(s2, s3));
        }
        mx_a = fmaxf(mx_a, __shfl_xor_sync(0xffffffffu, mx_a, 1));
        mx_a = fmaxf(mx_a, __shfl_xor_sync(0xffffffffu, mx_a, 2));
        mx_b = fmaxf(mx_b, __shfl_xor_sync(0xffffffffu, mx_b, 1));
        mx_b = fmaxf(mx_b, __shfl_xor_sync(0xffffffffu, mx_b, 2));

        float mn_a = fmaxf(m_a, mx_a), mn_b = fmaxf(m_b, mx_b);
        float ca = __expf(m_a - mn_a), cb = __expf(m_b - mn_b);
        m_a = mn_a; m_b = mn_b;

        float sum_a = 0.f, sum_b = 0.f;
        uint32_t pah[4][4], pal[4][4];
#pragma unroll
        for (int nt = 0; nt < 8; nt++) {
            float p0 = __expf(sacc[nt][0] - mn_a);
            float p1 = __expf(sacc[nt][1] - mn_a);
            float p2 = __expf(sacc[nt][2] - mn_b);
            float p3 = __expf(sacc[nt][3] - mn_b);
            sum_a += p0 + p1; sum_b += p2 + p3;
            __half h0 = __float2half_rn(p0), h1 = __float2half_rn(p1);
            __half h2 = __float2half_rn(p2), h3 = __float2half_rn(p3);
            __half e0 = __float2half_rn(p0 - __half2float(h0));
            __half e1 = __float2half_rn(p1 - __half2float(h1));
            __half e2 = __float2half_rn(p2 - __half2float(h2));
            __half e3 = __float2half_rn(p3 - __half2float(h3));
            int ks = nt >> 1, sel = (nt & 1) * 2;
            pah[ks][sel + 0] = pack_hh(h0, h1);
            pah[ks][sel + 1] = pack_hh(h2, h3);
            pal[ks][sel + 0] = pack_hh(e0, e1);
            pal[ks][sel + 1] = pack_hh(e2, e3);
        }
        sum_a += __shfl_xor_sync(0xffffffffu, sum_a, 1);
        sum_a += __shfl_xor_sync(0xffffffffu, sum_a, 2);
        sum_b += __shfl_xor_sync(0xffffffffu, sum_b, 1);
        sum_b += __shfl_xor_sync(0xffffffffu, sum_b, 2);
        l_a = l_a * ca + sum_a;
        l_b = l_b * cb + sum_b;

#pragma unroll
        for (int nt = 0; nt < 16; nt++) {
            oacc[nt][0] *= ca; oacc[nt][1] *= ca;
            oacc[nt][2] *= cb; oacc[nt][3] *= cb;
        }

        // ---- O += P V (ph*vh + ph*vl + pl*vh) ----
#pragma unroll
        for (int ks = 0; ks < 4; ks++) {
#pragma unroll
            for (int np = 0; np < 8; np++) {
                uint32_t vhf[4], vlf[4];
                ldsm_x4_t(vhf, aVh + ks * (16 * HDP * 2) + np * 32);
                ldsm_x4_t(vlf, aVl + ks * (16 * HDP * 2) + np * 32);
                mma_f16(oacc[2 * np],     pah[ks], vhf[0], vhf[1]);
                mma_f16(oacc[2 * np],     pah[ks], vlf[0], vlf[1]);
                mma_f16(oacc[2 * np],     pal[ks], vhf[0], vhf[1]);
                mma_f16(oacc[2 * np + 1], pah[ks], vhf[2], vhf[3]);
                mma_f16(oacc[2 * np + 1], pah[ks], vlf[2], vlf[3]);
                mma_f16(oacc[2 * np + 1], pal[ks], vhf[2], vhf[3]);
            }
        }
    }

    // ---- epilogue ----
    float ia = 1.f / l_a, ib = 1.f / l_b;
    float* outa = go + (size_t)row_a * OD + h * HD;
    float* outb = outa + (size_t)8 * OD;
#pragma unroll
    for (int nt = 0; nt < 16; nt++) {
        *(float2*)&outa[nt * 8 + 2 * t] = make_float2(oacc[nt][0] * ia, oacc[nt][1] * ia);
        *(float2*)&outb[nt * 8 + 2 * t] = make_float2(oacc[nt][2] * ib, oacc[nt][3] * ib);
    }
}

// ---------------- launch -----------------------------------------------------
extern "C" void kernel_launch(void* const* d_in, const int* in_sizes, int n_in,
                              void* d_out, int out_size)
{
    const float* hidden    = (const float*)d_in[0];
    const int*   positions = (const int*)  d_in[1];
    const float* qkv_w     = (const float*)d_in[2];
    const float* q_norm_w  = (const float*)d_in[3];
    const float* k_norm_w  = (const float*)d_in[4];
    const float* o_proj_w  = (const float*)d_in[5];
    float* out = (float*)d_out;

    float *p_qkv, *p_o;
    __half *p_qh, *p_ql, *p_kh, *p_kl, *p_vh, *p_vl;
    cudaGetSymbolAddress((void**)&p_qkv, g_qkv);
    cudaGetSymbolAddress((void**)&p_o,   g_o);
    cudaGetSymbolAddress((void**)&p_qh,  g_qh);
    cudaGetSymbolAddress((void**)&p_ql,  g_ql);
    cudaGetSymbolAddress((void**)&p_kh,  g_kh);
    cudaGetSymbolAddress((void**)&p_kl,  g_kl);
    cudaGetSymbolAddress((void**)&p_vh,  g_vh);
    cudaGetSymbolAddress((void**)&p_vl,  g_vl);

    cudaFuncSetAttribute(attn_mma, cudaFuncAttributeMaxDynamicSharedMemorySize, ATTN_SMEM);

    // 1) QKV GEMM
    gemm_hmma<<<dim3(QKV_N / 128, S_LEN / 128), 256>>>(hidden, qkv_w, p_qkv,
                                                       S_LEN, QKV_N, HIDDEN);

    // 2) RMSNorm + RoPE + hi/lo fp16 scatter
    norm_rope<<<dim3(HEADS, S_LEN), 128>>>(p_qkv, positions, q_norm_w, k_norm_w);

    // 3) tensor-core causal flash attention
    attn_mma<<<dim3(S_LEN / BQ, HEADS), 256, ATTN_SMEM>>>(p_qh, p_ql, p_kh, p_kl,
                                                          p_vh, p_vl, p_o);

    // 4) O projection
    gemm_hmma<<<dim3(HIDDEN / 128, S_LEN / 128), 256>>>(p_o, o_proj_w, out,
                                                        S_LEN, HIDDEN, OD);
}

// round 7
// speedup vs baseline: 4.9827x; 1.5772x over previous
#include <cuda_runtime.h>
#include <cuda_fp16.h>
#include <math.h>
#include <cstdint>

#define S_LEN   2048
#define HIDDEN  2048
#define HEADS   32
#define HD      128
#define QKV_N   (3 * HEADS * HD)   // 12288
#define OD      (HEADS * HD)       // 4096

// ---------------- scratch ---------------------------------------------------
__device__ float  g_qkv[(size_t)S_LEN * QKV_N];
__device__ float  g_o[(size_t)S_LEN * OD];
#define HSZ ((size_t)HEADS * S_LEN * HD)
__device__ __half g_qh[HSZ], g_ql[HSZ];
__device__ __half g_kh[HSZ], g_kl[HSZ];
__device__ __half g_vh[HSZ];

// ---------------- helpers ----------------------------------------------------
__device__ __forceinline__ uint32_t smem_u32(const void* p) {
    uint32_t a;
    asm("{ .reg .u64 t; cvta.to.shared.u64 t, %1; cvt.u32.u64 %0, t; }" : "=r"(a) : "l"(p));
    return a;
}
__device__ __forceinline__ uint32_t pack_h2(float a, float b) {
    __half2 h = __floats2half2_rn(a, b);
    return *reinterpret_cast<uint32_t*>(&h);
}
__device__ __forceinline__ uint32_t pack_hh(__half a, __half b) {
    __half2 h = __halves2half2(a, b);
    return *reinterpret_cast<uint32_t*>(&h);
}
__device__ __forceinline__ void mma_f16(float* d, const uint32_t* a,
                                        uint32_t b0, uint32_t b1) {
    asm volatile(
        "mma.sync.aligned.m16n8k16.row.col.f32.f16.f16.f32 "
        "{%0,%1,%2,%3}, {%4,%5,%6,%7}, {%8,%9}, {%0,%1,%2,%3};"
        : "+f"(d[0]), "+f"(d[1]), "+f"(d[2]), "+f"(d[3])
        : "r"(a[0]), "r"(a[1]), "r"(a[2]), "r"(a[3]), "r"(b0), "r"(b1));
}
__device__ __forceinline__ void ldsm_x4(uint32_t* r, uint32_t addr) {
    asm volatile("ldmatrix.sync.aligned.m8n8.x4.shared.b16 {%0,%1,%2,%3}, [%4];"
        : "=r"(r[0]), "=r"(r[1]), "=r"(r[2]), "=r"(r[3]) : "r"(addr));
}
__device__ __forceinline__ void ldsm_x4_t(uint32_t* r, uint32_t addr) {
    asm volatile("ldmatrix.sync.aligned.m8n8.x4.trans.shared.b16 {%0,%1,%2,%3}, [%4];"
        : "=r"(r[0]), "=r"(r[1]), "=r"(r[2]), "=r"(r[3]) : "r"(addr));
}
__device__ __forceinline__ void cp16(uint32_t s, const void* g) {
    asm volatile("cp.async.cg.shared.global [%0], [%1], 16;" :: "r"(s), "l"(g));
}
__device__ __forceinline__ void cp_commit() {
    asm volatile("cp.async.commit_group;" ::: "memory");
}
template <int N> __device__ __forceinline__ void cp_wait() {
    asm volatile("cp.async.wait_group %0;" :: "n"(N) : "memory");
}

// ---------------- fp16 HMMA GEMM NT (unchanged from R5) ----------------------
#define BKG  32
#define KPAD 40

__global__ __launch_bounds__(256) void gemm_hmma(const float* __restrict__ A,
                                                 const float* __restrict__ B,
                                                 float* __restrict__ C,
                                                 int M, int N, int K)
{
    __shared__ uint16_t As[128 * KPAD];
    __shared__ uint16_t Bs[128 * KPAD];

    const int tid  = threadIdx.x;
    const int wid  = tid >> 5;
    const int lane = tid & 31;
    const int g    = lane >> 2;
    const int t    = lane & 3;
    const int wm   = (wid >> 2) * 64;
    const int wn   = (wid & 3) * 32;
    const int bm0  = blockIdx.y * 128;
    const int bn0  = blockIdx.x * 128;

    float acc[4][4][4];
#pragma unroll
    for (int i = 0; i < 4; i++)
#pragma unroll
        for (int j = 0; j < 4; j++)
#pragma unroll
            for (int r = 0; r < 4; r++) acc[i][j][r] = 0.f;

    for (int k0 = 0; k0 < K; k0 += BKG) {
#pragma unroll
        for (int i = 0; i < 4; i++) {
            int idx = tid + i * 256;
            int r   = idx >> 3;
            int c4  = (idx & 7) * 4;
            float4 va = *(const float4*)&A[(size_t)(bm0 + r) * K + k0 + c4];
            *(uint2*)&As[r * KPAD + c4] = make_uint2(pack_h2(va.x, va.y), pack_h2(va.z, va.w));
            float4 vb = *(const float4*)&B[(size_t)(bn0 + r) * K + k0 + c4];
            *(uint2*)&Bs[r * KPAD + c4] = make_uint2(pack_h2(vb.x, vb.y), pack_h2(vb.z, vb.w));
        }
        __syncthreads();

#pragma unroll
        for (int kk = 0; kk < BKG; kk += 16) {
            uint32_t af[4][4], bf[4][2];
#pragma unroll
            for (int mt = 0; mt < 4; mt++) {
                int rb = wm + mt * 16;
                af[mt][0] = *(const uint32_t*)&As[(rb + g    ) * KPAD + kk + 2 * t    ];
                af[mt][1] = *(const uint32_t*)&As[(rb + g + 8) * KPAD + kk + 2 * t    ];
                af[mt][2] = *(const uint32_t*)&As[(rb + g    ) * KPAD + kk + 2 * t + 8];
                af[mt][3] = *(const uint32_t*)&As[(rb + g + 8) * KPAD + kk + 2 * t + 8];
            }
#pragma unroll
            for (int nt = 0; nt < 4; nt++) {
                int nb = wn + nt * 8;
                bf[nt][0] = *(const uint32_t*)&Bs[(nb + g) * KPAD + kk + 2 * t    ];
                bf[nt][1] = *(const uint32_t*)&Bs[(nb + g) * KPAD + kk + 2 * t + 8];
            }
#pragma unroll
            for (int mt = 0; mt < 4; mt++)
#pragma unroll
                for (int nt = 0; nt < 4; nt++)
                    mma_f16(acc[mt][nt], af[mt], bf[nt][0], bf[nt][1]);
        }
        __syncthreads();
    }

#pragma unroll
    for (int mt = 0; mt < 4; mt++) {
        int row0 = bm0 + wm + mt * 16 + g;
#pragma unroll
        for (int nt = 0; nt < 4; nt++) {
            int col = bn0 + wn + nt * 8 + 2 * t;
            *(float2*)&C[(size_t)row0 * N + col] = make_float2(acc[mt][nt][0], acc[mt][nt][1]);
            *(float2*)&C[(size_t)(row0 + 8) * N + col] = make_float2(acc[mt][nt][2], acc[mt][nt][3]);
        }
    }
}

// ---------------- RMSNorm + RoPE (all fp32) + hi/lo scatter ------------------
__device__ __forceinline__ void split_store(__half* ph, __half* pl, size_t i, float x) {
    __half h = __float2half_rn(x);
    ph[i] = h;
    pl[i] = __float2half_rn(x - __half2float(h));
}

__global__ __launch_bounds__(128) void norm_rope(const float* __restrict__ qkv,
                                                 const int* __restrict__ positions,
                                                 const float* __restrict__ qw,
                                                 const float* __restrict__ kw)
{
    const int h = blockIdx.x;
    const int s = blockIdx.y;
    const int d = threadIdx.x;

    const float* base = qkv + (size_t)s * QKV_N + h * HD;
    float qv = base[d];
    float kv = base[HEADS * HD + d];
    float vv = base[2 * HEADS * HD + d];

    float q2 = qv * qv, k2 = kv * kv;
#pragma unroll
    for (int off = 16; off > 0; off >>= 1) {
        q2 += __shfl_xor_sync(0xffffffffu, q2, off);
        k2 += __shfl_xor_sync(0xffffffffu, k2, off);
    }
    __shared__ float sq[4], sk[4];
    int wid = d >> 5, lane = d & 31;
    if (lane == 0) { sq[wid] = q2; sk[wid] = k2; }
    __syncthreads();
    q2 = sq[0] + sq[1] + sq[2] + sq[3];
    k2 = sk[0] + sk[1] + sk[2] + sk[3];

    float qn = qv * rsqrtf(q2 * (1.f / HD) + 1e-5f) * qw[d];
    float kn = kv * rsqrtf(k2 * (1.f / HD) + 1e-5f) * kw[d];

    __shared__ float qs[HD], ks[HD];
    qs[d] = qn; ks[d] = kn;
    __syncthreads();

    const size_t out = ((size_t)h * S_LEN + s) * HD;
    {
        __half hv = __float2half_rn(vv);
        g_vh[out + d] = hv;
    }

    if (d < HD / 2) {
        int p = positions[s];
        // fp32 path matching reference arithmetic (inv_freq fp32, product fp32)
        float inv = expf(-9.210340371976184f * (float)(2 * d) * (1.0f / HD));
        float ang = (float)p * inv;
        float c, sn;
        sincosf(ang, &sn, &c);   // accurate sincos (internal range reduction)

        float q1 = qs[d], q2v = qs[d + HD / 2];
        float k1 = ks[d], k2v = ks[d + HD / 2];
        split_store(g_qh, g_ql, out + d,          q1 * c - q2v * sn);
        split_store(g_qh, g_ql, out + d + HD / 2, q2v * c + q1 * sn);
        split_store(g_kh, g_kl, out + d,          k1 * c - k2v * sn);
        split_store(g_kh, g_kl, out + d + HD / 2, k2v * c + k1 * sn);
    }
}

// ---------------- tensor-core flash attention --------------------------------
// Q hi/lo + K hi/lo (3-term QK), V hi only (2-term PV). cp.async double buffer.
#define BQ  128
#define BK  64
#define HDP 136                      // 272B row stride, ldmatrix conflict-free
#define BUF_H (3 * BK * HDP)         // Kh | Kl | Vh per buffer
#define ATTN_SMEM ((2 * BQ * HDP + 2 * BUF_H) * 2)   // 174080 bytes

__global__ __launch_bounds__(256) void attn_mma(const __half* __restrict__ qh,
                                                const __half* __restrict__ ql,
                                                const __half* __restrict__ kh,
                                                const __half* __restrict__ kl,
                                                const __half* __restrict__ vh,
                                                float* __restrict__ go)
{
    extern __shared__ __half sh[];
    __half* Qh = sh;
    __half* Ql = Qh + BQ * HDP;

    const int tid = threadIdx.x;
    const int wq  = tid >> 5;
    const int l   = tid & 31;
    const int t   = l & 3;
    const int g   = l >> 2;
    const int qb  = gridDim.x - 1 - blockIdx.x;   // heavy blocks first
    const int h   = blockIdx.y;
    const int rb  = wq * 16;
    const float scale = 0.08838834764831845f;

    // Q hi/lo tile (plain loads, once)
    const size_t qoff = ((size_t)h * S_LEN + (size_t)qb * BQ) * HD;
    for (int idx = tid; idx < BQ * HD / 8; idx += 256) {
        int r = idx >> 4, c = (idx & 15) * 8;
        *(uint4*)&Qh[r * HDP + c] = *(const uint4*)&qh[qoff + r * HD + c];
        *(uint4*)&Ql[r * HDP + c] = *(const uint4*)&ql[qoff + r * HD + c];
    }

    const uint32_t smb  = smem_u32(sh);
    const uint32_t bufb = smb + (uint32_t)(2 * BQ * HDP) * 2;   // byte addr of buf0
    const size_t hbase  = (size_t)h * S_LEN * HD;

    // cp.async lane targets: 4 chunks per array per thread
    const int cr = tid >> 4;            // row group base
    const int cc = (tid & 15) * 8;      // halves

    const int nkt = 2 * qb + 2;

    // preload tile 0 into buffer 0
    {
        const size_t gk = hbase;
#pragma unroll
        for (int i = 0; i < 4; i++) {
            int r = cr + i * 16;
            uint32_t d0 = bufb + (uint32_t)(r * HDP + cc) * 2;
            cp16(d0,                        &kh[gk + r * HD + cc]);
            cp16(d0 + BK * HDP * 2,         &kl[gk + r * HD + cc]);
            cp16(d0 + 2 * BK * HDP * 2,     &vh[gk + r * HD + cc]);
        }
        cp_commit();
    }

    float oacc[16][4];
#pragma unroll
    for (int i = 0; i < 16; i++)
#pragma unroll
        for (int j = 0; j < 4; j++) oacc[i][j] = 0.f;
    float m_a = -1e30f, m_b = -1e30f, l_a = 0.f, l_b = 0.f;

    // per-lane ldmatrix lane-offsets (halves)
    const int frag  = (l & 7) + 8 * ((l >> 3) & 1);
    const int qvoff = frag * HDP + 8 * (l >> 4);                          // A-frag / trans-B
    const int koff  = ((l & 7) + 8 * (l >> 4)) * HDP + 8 * ((l >> 3) & 1); // B-frag
    const uint32_t aQh = smb + (uint32_t)(rb * HDP + qvoff) * 2;
    const uint32_t aQl = aQh + BQ * HDP * 2;

    const int row_a = qb * BQ + rb + g;
    const int row_b = row_a + 8;

    for (int kb = 0; kb < nkt; kb++) {
        const uint32_t cb = bufb + (uint32_t)((kb & 1) * BUF_H) * 2;

        // issue next tile into other buffer
        if (kb + 1 < nkt) {
            const size_t gk = hbase + (size_t)(kb + 1) * BK * HD;
            const uint32_t nb = bufb + (uint32_t)(((kb + 1) & 1) * BUF_H) * 2;
#pragma unroll
            for (int i = 0; i < 4; i++) {
                int r = cr + i * 16;
                uint32_t d0 = nb + (uint32_t)(r * HDP + cc) * 2;
                cp16(d0,                    &kh[gk + r * HD + cc]);
                cp16(d0 + BK * HDP * 2,     &kl[gk + r * HD + cc]);
                cp16(d0 + 2 * BK * HDP * 2, &vh[gk + r * HD + cc]);
            }
            cp_commit();
            cp_wait<1>();   // current tile complete (next may remain in flight)
        } else {
            cp_wait<0>();
        }
        __syncthreads();    // current buffer visible to all warps (incl. Q on kb==0)

        const uint32_t aKh = cb + (uint32_t)koff * 2;
        const uint32_t aKl = aKh + BK * HDP * 2;
        const uint32_t aVh = cb + (uint32_t)(2 * BK * HDP + qvoff) * 2;

        // ---- S = Q K^T : hi*hi + hi*lo + lo*hi ----
        float sacc[8][4];
#pragma unroll
        for (int i = 0; i < 8; i++)
#pragma unroll
            for (int j = 0; j < 4; j++) sacc[i][j] = 0.f;

#pragma unroll
        for (int ks = 0; ks < 8; ks++) {
            uint32_t qhf[4], qlf[4];
            ldsm_x4(qhf, aQh + ks * 32);
            ldsm_x4(qlf, aQl + ks * 32);
#pragma unroll
            for (int np = 0; np < 4; np++) {
                uint32_t khf[4], klf[4];
                ldsm_x4(khf, aKh + np * (16 * HDP * 2) + ks * 32);
                ldsm_x4(klf, aKl + np * (16 * HDP * 2) + ks * 32);
                // interleave across the two accumulators (2 independent chains)
                mma_f16(sacc[2 * np],     qhf, khf[0], khf[1]);
                mma_f16(sacc[2 * np + 1], qhf, khf[2], khf[3]);
                mma_f16(sacc[2 * np],     qhf, klf[0], klf[1]);
                mma_f16(sacc[2 * np + 1], qhf, klf[2], klf[3]);
                mma_f16(sacc[2 * np],     qlf, khf[0], khf[1]);
                mma_f16(sacc[2 * np + 1], qlf, khf[2], khf[3]);
            }
        }

        // ---- scale + causal mask + online softmax ----
        float mx_a = -1e30f, mx_b = -1e30f;
#pragma unroll
        for (int nt = 0; nt < 8; nt++) {
            int c0 = kb * BK + nt * 8 + 2 * t, c1 = c0 + 1;
            float s0 = sacc[nt][0] * scale; if (c0 > row_a) s0 = -1e30f;
            float s1 = sacc[nt][1] * scale; if (c1 > row_a) s1 = -1e30f;
            float s2 = sacc[nt][2] * scale; if (c0 > row_b) s2 = -1e30f;
            float s3 = sacc[nt][3] * scale; if (c1 > row_b) s3 = -1e30f;
            sacc[nt][0] = s0; sacc[nt][1] = s1; sacc[nt][2] = s2; sacc[nt][3] = s3;
            mx_a = fmaxf(mx_a, fmaxf(s0, s1));
            mx_b = fmaxf(mx_b, fmaxf(s2, s3));
        }
        mx_a = fmaxf(mx_a, __shfl_xor_sync(0xffffffffu, mx_a, 1));
        mx_a = fmaxf(mx_a, __shfl_xor_sync(0xffffffffu, mx_a, 2));
        mx_b = fmaxf(mx_b, __shfl_xor_sync(0xffffffffu, mx_b, 1));
        mx_b = fmaxf(mx_b, __shfl_xor_sync(0xffffffffu, mx_b, 2));

        float mn_a = fmaxf(m_a, mx_a), mn_b = fmaxf(m_b, mx_b);
        float ca = __expf(m_a - mn_a), cb2 = __expf(m_b - mn_b);
        m_a = mn_a; m_b = mn_b;

        float sum_a = 0.f, sum_b = 0.f;
        uint32_t pah[4][4], pal[4][4];
#pragma unroll
        for (int nt = 0; nt < 8; nt++) {
            float p0 = __expf(sacc[nt][0] - mn_a);
            float p1 = __expf(sacc[nt][1] - mn_a);
            float p2 = __expf(sacc[nt][2] - mn_b);
            float p3 = __expf(sacc[nt][3] - mn_b);
            sum_a += p0 + p1; sum_b += p2 + p3;
            __half h0 = __float2half_rn(p0), h1 = __float2half_rn(p1);
            __half h2 = __float2half_rn(p2), h3 = __float2half_rn(p3);
            __half e0 = __float2half_rn(p0 - __half2float(h0));
            __half e1 = __float2half_rn(p1 - __half2float(h1));
            __half e2 = __float2half_rn(p2 - __half2float(h2));
            __half e3 = __float2half_rn(p3 - __half2float(h3));
            int ks = nt >> 1, sel = (nt & 1) * 2;
            pah[ks][sel + 0] = pack_hh(h0, h1);
            pah[ks][sel + 1] = pack_hh(h2, h3);
            pal[ks][sel + 0] = pack_hh(e0, e1);
            pal[ks][sel + 1] = pack_hh(e2, e3);
        }
        sum_a += __shfl_xor_sync(0xffffffffu, sum_a, 1);
        sum_a += __shfl_xor_sync(0xffffffffu, sum_a, 2);
        sum_b += __shfl_xor_sync(0xffffffffu, sum_b, 1);
        sum_b += __shfl_xor_sync(0xffffffffu, sum_b, 2);
        l_a = l_a * ca + sum_a;
        l_b = l_b * cb2 + sum_b;

#pragma unroll
        for (int nt = 0; nt < 16; nt++) {
            oacc[nt][0] *= ca;  oacc[nt][1] *= ca;
            oacc[nt][2] *= cb2; oacc[nt][3] *= cb2;
        }

        // ---- O += P V : (P_hi + P_lo) * V_hi ----
#pragma unroll
        for (int ks = 0; ks < 4; ks++) {
#pragma unroll
            for (int np = 0; np < 8; np++) {
                uint32_t vhf[4];
                ldsm_x4_t(vhf, aVh + ks * (16 * HDP * 2) + np * 32);
                mma_f16(oacc[2 * np],     pah[ks], vhf[0], vhf[1]);
                mma_f16(oacc[2 * np + 1], pah[ks], vhf[2], vhf[3]);
                mma_f16(oacc[2 * np],     pal[ks], vhf[0], vhf[1]);
                mma_f16(oacc[2 * np + 1], pal[ks], vhf[2], vhf[3]);
            }
        }
        __syncthreads();   // all warps done reading this buffer before next overwrite
    }

    // ---- epilogue ----
    float ia = 1.f / l_a, ib = 1.f / l_b;
    float* outa = go + (size_t)row_a * OD + h * HD;
    float* outb = outa + (size_t)8 * OD;
#pragma unroll
    for (int nt = 0; nt < 16; nt++) {
        *(float2*)&outa[nt * 8 + 2 * t] = make_float2(oacc[nt][0] * ia, oacc[nt][1] * ia);
        *(float2*)&outb[nt * 8 + 2 * t] = make_float2(oacc[nt][2] * ib, oacc[nt][3] * ib);
    }
}

// ---------------- launch -----------------------------------------------------
extern "C" void kernel_launch(void* const* d_in, const int* in_sizes, int n_in,
                              void* d_out, int out_size)
{
    const float* hidden    = (const float*)d_in[0];
    const int*   positions = (const int*)  d_in[1];
    const float* qkv_w     = (const float*)d_in[2];
    const float* q_norm_w  = (const float*)d_in[3];
    const float* k_norm_w  = (const float*)d_in[4];
    const float* o_proj_w  = (const float*)d_in[5];
    float* out = (float*)d_out;

    float *p_qkv, *p_o;
    __half *p_qh, *p_ql, *p_kh, *p_kl, *p_vh;
    cudaGetSymbolAddress((void**)&p_qkv, g_qkv);
    cudaGetSymbolAddress((void**)&p_o,   g_o);
    cudaGetSymbolAddress((void**)&p_qh,  g_qh);
    cudaGetSymbolAddress((void**)&p_ql,  g_ql);
    cudaGetSymbolAddress((void**)&p_kh,  g_kh);
    cudaGetSymbolAddress((void**)&p_kl,  g_kl);
    cudaGetSymbolAddress((void**)&p_vh,  g_vh);

    cudaFuncSetAttribute(attn_mma, cudaFuncAttributeMaxDynamicSharedMemorySize, ATTN_SMEM);

    // 1) QKV GEMM
    gemm_hmma<<<dim3(QKV_N / 128, S_LEN / 128), 256>>>(hidden, qkv_w, p_qkv,
                                                       S_LEN, QKV_N, HIDDEN);

    // 2) RMSNorm + RoPE (fp32) + hi/lo scatter
    norm_rope<<<dim3(HEADS, S_LEN), 128>>>(p_qkv, positions, q_norm_w, k_norm_w);

    // 3) tensor-core causal flash attention (cp.async double-buffered)
    attn_mma<<<dim3(S_LEN / BQ, HEADS), 256, ATTN_SMEM>>>(p_qh, p_ql, p_kh, p_kl,
                                                          p_vh, p_o);

    // 4) O projection
    gemm_hmma<<<dim3(HIDDEN / 128, S_LEN / 128), 256>>>(p_o, o_proj_w, out,
                                                        S_LEN, HIDDEN, OD);
}